// round 15
// baseline (speedup 1.0000x reference)
#include <cuda_runtime.h>
#include <cuda_fp16.h>
#include <cstdint>

#define B_  1024
#define N_  128
#define H_  128
#define FE_ 8
#define G3_ 384
#define KX_ 136
#define KSTEPS 9         // K = 144 (128 h + 8 jets + 8 zero)

// ---------------- device scratch ----------------
__device__ __align__(16) float g_hs[B_ * H_];
__device__ __align__(16) float g_bias[B_ * G3_];
// B_hi in MMA-fragment order (fp16): [ks][pair p (24)][lane (32)] uint4
// ks=8 includes jets cols for ALL gates (n-gate block consumed into accJ)
__device__ __align__(16) uint4 g_Bp[KSTEPS * 768];

__device__ __forceinline__ uint32_t pack_h2(float a, float b) {
    __half2 p = __float22half2_rn(make_float2(a, b));   // single cvt.rn.f16x2.f32
    return *(uint32_t*)&p;
}
__device__ __forceinline__ float tanh_ap(float x) {
    float y;
    asm("tanh.approx.f32 %0, %1;" : "=f"(y) : "f"(x));
    return y;
}
__device__ __forceinline__ uint32_t smem_u32(const void* p) {
    uint32_t a;
    asm("{ .reg .u64 t; cvta.to.shared.u64 t, %1; cvt.u32.u64 %0, t; }" : "=r"(a) : "l"(p));
    return a;
}
__device__ __forceinline__ void ldm_x4(uint32_t* r, uint32_t addr) {
    asm volatile("ldmatrix.sync.aligned.m8n8.x4.shared.b16 {%0,%1,%2,%3}, [%4];"
                 : "=r"(r[0]), "=r"(r[1]), "=r"(r[2]), "=r"(r[3]) : "r"(addr));
}
__device__ __forceinline__ void griddep_wait() {
    asm volatile("griddepcontrol.wait;" ::: "memory");
}

#define MMA16816(ac, a0, a1, a2, a3, b0, b1)                                   \
    asm volatile("mma.sync.aligned.m16n8k16.row.col.f32.f16.f16.f32 "          \
                 "{%0,%1,%2,%3}, {%4,%5,%6,%7}, {%8,%9}, {%0,%1,%2,%3};"       \
                 : "+f"((ac)[0]), "+f"((ac)[1]), "+f"((ac)[2]), "+f"((ac)[3])  \
                 : "r"(a0), "r"(a1), "r"(a2), "r"(a3), "r"(b0), "r"(b1))

// ---------------- k_pre1 ----------------
// blocks [0, B_): pure-bandwidth rowsum -> g_hs
// blocks [B_, B_+54): weight permute into fp16 fragment order
__global__ void __launch_bounds__(256) k_pre1(
    const float* __restrict__ h,
    const float* __restrict__ Whh, const float* __restrict__ Wih)
{
    const int bid = blockIdx.x;
    const int tid = threadIdx.x;

    if (bid >= B_) {
        int i = (bid - B_) * 256 + tid;           // < 13824 = KSTEPS*1536
        int ks = i / 1536, rem = i % 1536;
        int nt = rem >> 5, lane = rem & 31;
        int n = nt * 8 + (lane >> 2);
        int k0 = ks * 16 + (lane & 3) * 2;
        float w[4];
        #pragma unroll
        for (int q = 0; q < 4; q++) {
            int k = k0 + (q >> 1) * 8 + (q & 1);
            float v = 0.f;
            if (k < H_) v = Whh[n * H_ + k];
            else if (k < H_ + FE_) v = Wih[(size_t)n * KX_ + k];   // jets cols, ALL gates
            w[q] = v;
        }
        uint2 hiv = make_uint2(pack_h2(w[0], w[1]), pack_h2(w[2], w[3]));
        uint2* bp = (uint2*)g_Bp;
        int p = nt >> 1, half = nt & 1;
        bp[(ks * 768 + p * 32 + lane) * 2 + half] = hiv;
        return;
    }

    __shared__ float4 red[256];
    const int b = bid;
    {
        int k4 = tid & 31, n0 = tid >> 5;
        const float4* p = (const float4*)(h + (size_t)b * N_ * H_) + k4;
        float4 s = make_float4(0.f, 0.f, 0.f, 0.f);
        #pragma unroll
        for (int j = 0; j < 16; j++) {
            float4 v = p[(size_t)(n0 + 8 * j) * 32];
            s.x += v.x; s.y += v.y; s.z += v.z; s.w += v.w;
        }
        red[tid] = s;
    }
    __syncthreads();
    #pragma unroll
    for (int off = 128; off >= 32; off >>= 1) {
        if (tid < off) {
            float4 a = red[tid], c = red[tid + off];
            a.x += c.x; a.y += c.y; a.z += c.z; a.w += c.w;
            red[tid] = a;
        }
        __syncthreads();
    }
    if (tid < 32) ((float4*)g_hs)[b * 32 + tid] = red[tid];
}

// ---------------- k_pre2: message + bias, 64 blocks x 16 batches (PDL) ----------------
__global__ void __launch_bounds__(256) k_pre2(
    const float* __restrict__ Wm, const float* __restrict__ bm,
    const float* __restrict__ Wih, const float* __restrict__ bih,
    const float* __restrict__ bhh)
{
    __shared__ float hsS[16 * H_];    // 8 KB
    __shared__ float msgS[16 * H_];   // 8 KB
    const int tid = threadIdx.x;
    const int b0 = blockIdx.x * 16;

    griddep_wait();   // g_hs produced by k_pre1

    for (int i = tid; i < 16 * 32; i += 256)
        ((float4*)hsS)[i] = ((const float4*)(g_hs + (size_t)b0 * H_))[i];
    __syncthreads();

    {
        const int k   = tid & 127;
        const int bh8 = (tid >> 7) * 8;
        const float4* wr = (const float4*)(Wm + (size_t)k * H_);
        float acc[8];
        #pragma unroll
        for (int b = 0; b < 8; b++) acc[b] = 0.f;
        #pragma unroll 8
        for (int j = 0; j < H_ / 4; j++) {
            float4 w = wr[j];
            #pragma unroll
            for (int b = 0; b < 8; b++) {
                const float* m = hsS + (bh8 + b) * H_ + 4 * j;
                acc[b] += m[0] * w.x + m[1] * w.y + m[2] * w.z + m[3] * w.w;
            }
        }
        float bb = (float)N_ * bm[k];
        #pragma unroll
        for (int b = 0; b < 8; b++)
            msgS[(bh8 + b) * H_ + k] = tanhf(acc[b] + bb);
    }
    __syncthreads();

    for (int g = tid; g < G3_; g += 256) {
        const float4* wr = (const float4*)(Wih + (size_t)g * KX_);
        float acc[16];
        #pragma unroll
        for (int b = 0; b < 16; b++) acc[b] = 0.f;
        #pragma unroll 8
        for (int j = 0; j < H_ / 4; j++) {
            float4 w = wr[j];
            #pragma unroll
            for (int b = 0; b < 16; b++) {
                const float* m = msgS + b * H_ + 4 * j;
                acc[b] += m[0] * w.x + m[1] * w.y + m[2] * w.z + m[3] * w.w;
            }
        }
        float base = bih[g] + ((g < 2 * H_) ? bhh[g] : 0.f);
        #pragma unroll
        for (int b = 0; b < 16; b++)
            g_bias[(size_t)(b0 + b) * G3_ + g] = acc[b] + base;
    }
}

// ---------------- smem layout for k_main (bytes) ----------------
#define OFF_AH   0            //  9728  A_hi [32][152] fp16, 304B row stride
#define OFF_BIAS 9728         //  1536
#define OFF_BHHN 11264        //   512
#define SMEM_SZ  11776

// ---------------- main: 256 threads, 32 rows x 384 cols per CTA, 2 CTAs/SM (PDL) ----------------
__global__ void __launch_bounds__(256, 2) k_main(
    const float* __restrict__ h, const float* __restrict__ jets,
    const float* __restrict__ bhh, float* __restrict__ out)
{
    extern __shared__ char smem[];
    const int tid  = threadIdx.x;
    const int wn   = tid >> 5;          // 8 N-positions: 16 cols per gate each
    const int lane = tid & 31;
    const int cta  = blockIdx.x;        // 32 rows each, 4 CTAs per batch
    const int batch = cta >> 2;
    const float* hTile = h + (size_t)cta * 32 * 128;

    // ======== upstream-independent prologue (overlaps pre1/pre2 via PDL) ========
    // ---- convert h -> A_hi only (epilogue re-reads exact h from gmem/L1) ----
    {
        const float4* hp = (const float4*)hTile;
        #pragma unroll
        for (int i = tid; i < 512; i += 256) {
            int row = i >> 4, q = i & 15;            // 8 cols per step
            float4 v0 = hp[(row << 5) + q * 2];
            float4 v1 = hp[(row << 5) + q * 2 + 1];
            uint4 hi4 = make_uint4(pack_h2(v0.x, v0.y), pack_h2(v0.z, v0.w),
                                   pack_h2(v1.x, v1.y), pack_h2(v1.z, v1.w));
            *(uint4*)(smem + OFF_AH + row * 304 + q * 16) = hi4;
        }
    }
    // ---- jets cols (A K 128..143) + zero pad to 152 ----
    if (tid < 32) {
        int row = tid;
        const float4* jp = (const float4*)(jets + (size_t)(cta * 32 + row) * FE_);
        float4 j0 = jp[0], j1 = jp[1];
        uint4 jh = make_uint4(pack_h2(j0.x, j0.y), pack_h2(j0.z, j0.w),
                              pack_h2(j1.x, j1.y), pack_h2(j1.z, j1.w));
        uint4 zz = make_uint4(0, 0, 0, 0);
        *(uint4*)(smem + OFF_AH + row * 304 + 256) = jh;
        *(uint4*)(smem + OFF_AH + row * 304 + 272) = zz;
        *(uint4*)(smem + OFF_AH + row * 304 + 288) = zz;
    }
    // ---- bhh_n (pure input, safe pre-wait) ----
    if (tid < 128)
        ((float*)(smem + OFF_BHHN))[tid] = bhh[2 * H_ + tid];

    // ======== wait for upstream grids (pre2 complete => pre1 complete) ========
    griddep_wait();

    for (int g = tid; g < G3_; g += 256)
        ((float*)(smem + OFF_BIAS))[g] = g_bias[(size_t)batch * G3_ + g];
    __syncthreads();   // the ONLY barrier

    // acc[gate][mt][j][frag] + accJ (jets . W_ihn, NOT scaled by r)
    float acc[3][2][2][4];
    float accJ[2][2][4];
    #pragma unroll
    for (int g = 0; g < 3; g++)
        #pragma unroll
        for (int m = 0; m < 2; m++)
            #pragma unroll
            for (int j = 0; j < 2; j++) {
                acc[g][m][j][0] = 0.f; acc[g][m][j][1] = 0.f;
                acc[g][m][j][2] = 0.f; acc[g][m][j][3] = 0.f;
            }
    #pragma unroll
    for (int m = 0; m < 2; m++)
        #pragma unroll
        for (int j = 0; j < 2; j++) {
            accJ[m][j][0] = 0.f; accJ[m][j][1] = 0.f;
            accJ[m][j][2] = 0.f; accJ[m][j][3] = 0.f;
        }

    const uint32_t sbA = smem_u32(smem) + OFF_AH
                       + (uint32_t)(lane & 15) * 304 + ((lane & 16) ? 16 : 0);
    const uint4* bBase = g_Bp + wn * 32 + lane;

    // ======== software-pipelined k-loop (1-deep A/B register double buffer) ========
    uint32_t ah[2][2][4];   // [buf][mt][frag]
    uint4    bf[2][3];      // [buf][gate]

    ldm_x4(ah[0][0], sbA);
    ldm_x4(ah[0][1], sbA + 16 * 304);
    bf[0][0] = bBase[0];
    bf[0][1] = bBase[256];
    bf[0][2] = bBase[512];

    #pragma unroll
    for (int ks = 0; ks < KSTEPS; ks++) {
        const int cur = ks & 1, nxt = cur ^ 1;
        if (ks < KSTEPS - 1) {
            // prefetch next k-step while current MMAs issue
            ldm_x4(ah[nxt][0], sbA + (ks + 1) * 32);
            ldm_x4(ah[nxt][1], sbA + 16 * 304 + (ks + 1) * 32);
            const uint4* bp = bBase + (ks + 1) * 768;
            bf[nxt][0] = bp[0];
            bf[nxt][1] = bp[256];
            bf[nxt][2] = bp[512];
        }
        #pragma unroll
        for (int g = 0; g < 3; g++) {
            uint4 bh = bf[cur][g];
            float (*dst)[2][4] = (ks == KSTEPS - 1 && g == 2) ? accJ : acc[g];
            #pragma unroll
            for (int mt = 0; mt < 2; mt++) {
                MMA16816(dst[mt][0], ah[cur][mt][0], ah[cur][mt][1], ah[cur][mt][2], ah[cur][mt][3], bh.x, bh.y);
                MMA16816(dst[mt][1], ah[cur][mt][0], ah[cur][mt][1], ah[cur][mt][2], ah[cur][mt][3], bh.z, bh.w);
            }
        }
    }

    // ---- GRU epilogue (warp-local, MUFU tanh; exact h re-read from gmem/L1) ----
    {
        const float* biasS = (const float*)(smem + OFF_BIAS);
        const float* bhhnS = (const float*)(smem + OFF_BHHN);
        const size_t mBase = (size_t)cta * 32;
        #pragma unroll
        for (int mt = 0; mt < 2; mt++) {
            #pragma unroll
            for (int half = 0; half < 2; half++) {
                const int row = mt * 16 + (lane >> 2) + half * 8;
                #pragma unroll
                for (int j = 0; j < 2; j++) {
                    const int c = wn * 16 + j * 8 + (lane & 3) * 2;
                    float2 hv2 = *(const float2*)(hTile + row * 128 + c);
                    float o[2];
                    #pragma unroll
                    for (int e = 0; e < 2; e++) {
                        const int g = c + e;
                        const int fr = half * 2 + e;
                        float aR = acc[0][mt][j][fr];
                        float aZ = acc[1][mt][j][fr];
                        float aN = acc[2][mt][j][fr];
                        float aJ = accJ[mt][j][fr];
                        float r = 0.5f * tanh_ap(0.5f * (aR + biasS[g])) + 0.5f;
                        float z = 0.5f * tanh_ap(0.5f * (aZ + biasS[128 + g])) + 0.5f;
                        float n = tanh_ap(aJ + biasS[256 + g] + r * (aN + bhhnS[g]));
                        float hv = e ? hv2.y : hv2.x;
                        o[e] = (1.f - z) * n + z * hv;
                    }
                    *(float2*)(out + (mBase + row) * 128 + c) = make_float2(o[0], o[1]);
                }
            }
        }
    }
}

extern "C" void kernel_launch(void* const* d_in, const int* in_sizes, int n_in,
                              void* d_out, int out_size) {
    const float* h    = (const float*)d_in[0];
    const float* jets = (const float*)d_in[1];
    // d_in[2] = mask (unused)
    const float* Wm   = (const float*)d_in[3];
    const float* bm   = (const float*)d_in[4];
    const float* Wih  = (const float*)d_in[5];
    const float* Whh  = (const float*)d_in[6];
    const float* bih  = (const float*)d_in[7];
    const float* bhh  = (const float*)d_in[8];
    float* out = (float*)d_out;

    cudaFuncSetAttribute(k_main, cudaFuncAttributeMaxDynamicSharedMemorySize, SMEM_SZ);

    // pre1: normal launch
    k_pre1<<<B_ + 54, 256>>>(h, Whh, Wih);

    // pre2 + k_main: programmatic dependent launch
    cudaLaunchAttribute attr[1];
    attr[0].id = cudaLaunchAttributeProgrammaticStreamSerialization;
    attr[0].val.programmaticStreamSerializationAllowed = 1;

    {
        cudaLaunchConfig_t cfg = {};
        cfg.gridDim = dim3(B_ / 16);
        cfg.blockDim = dim3(256);
        cfg.dynamicSmemBytes = 0;
        cfg.stream = 0;
        cfg.attrs = attr;
        cfg.numAttrs = 1;
        cudaLaunchKernelEx(&cfg, k_pre2, Wm, bm, Wih, bih, bhh);
    }
    {
        cudaLaunchConfig_t cfg = {};
        cfg.gridDim = dim3(4 * B_);
        cfg.blockDim = dim3(256);
        cfg.dynamicSmemBytes = SMEM_SZ;
        cfg.stream = 0;
        cfg.attrs = attr;
        cfg.numAttrs = 1;
        cudaLaunchKernelEx(&cfg, k_main, h, jets, bhh, out);
    }
}

// round 16
// speedup vs baseline: 1.0612x; 1.0612x over previous
#include <cuda_runtime.h>
#include <cuda_fp16.h>
#include <cstdint>

#define B_  1024
#define N_  128
#define H_  128
#define FE_ 8
#define G3_ 384
#define KX_ 136
#define KSTEPS 9         // K = 144 (128 h + 8 jets + 8 zero)

// ---------------- device scratch ----------------
__device__ __align__(16) float g_bias[B_ * G3_];
// B_hi in MMA-fragment order (fp16): [ks][pair p (24)][lane (32)] uint4
// ks=8 includes jets cols for ALL gates (n-gate block consumed into accJ)
__device__ __align__(16) uint4 g_Bp[KSTEPS * 768];

__device__ __forceinline__ uint32_t pack_h2(float a, float b) {
    __half2 p = __float22half2_rn(make_float2(a, b));   // single cvt.rn.f16x2.f32
    return *(uint32_t*)&p;
}
__device__ __forceinline__ float tanh_ap(float x) {
    float y;
    asm("tanh.approx.f32 %0, %1;" : "=f"(y) : "f"(x));
    return y;
}
__device__ __forceinline__ uint32_t smem_u32(const void* p) {
    uint32_t a;
    asm("{ .reg .u64 t; cvta.to.shared.u64 t, %1; cvt.u32.u64 %0, t; }" : "=r"(a) : "l"(p));
    return a;
}
__device__ __forceinline__ void ldm_x4(uint32_t* r, uint32_t addr) {
    asm volatile("ldmatrix.sync.aligned.m8n8.x4.shared.b16 {%0,%1,%2,%3}, [%4];"
                 : "=r"(r[0]), "=r"(r[1]), "=r"(r[2]), "=r"(r[3]) : "r"(addr));
}
__device__ __forceinline__ void griddep_wait() {
    asm volatile("griddepcontrol.wait;" ::: "memory");
}

#define MMA16816(ac, a0, a1, a2, a3, b0, b1)                                   \
    asm volatile("mma.sync.aligned.m16n8k16.row.col.f32.f16.f16.f32 "          \
                 "{%0,%1,%2,%3}, {%4,%5,%6,%7}, {%8,%9}, {%0,%1,%2,%3};"       \
                 : "+f"((ac)[0]), "+f"((ac)[1]), "+f"((ac)[2]), "+f"((ac)[3])  \
                 : "r"(a0), "r"(a1), "r"(a2), "r"(a3), "r"(b0), "r"(b1))

// ---------------- k_pre (fused): rowsum + message + bias, and weight permute ----------------
// blocks [0, 256): 4 batches each -> rowsum from h -> message tanh -> gate bias
// blocks [256, 310): weight permute into fp16 fragment order
__global__ void __launch_bounds__(256) k_pre(
    const float* __restrict__ h,
    const float* __restrict__ Whh, const float* __restrict__ Wih,
    const float* __restrict__ Wm, const float* __restrict__ bm,
    const float* __restrict__ bih, const float* __restrict__ bhh)
{
    const int bid = blockIdx.x;
    const int tid = threadIdx.x;

    if (bid >= 256) {
        // ---- weight permute ----
        int i = (bid - 256) * 256 + tid;          // < 13824 = KSTEPS*1536
        int ks = i / 1536, rem = i % 1536;
        int nt = rem >> 5, lane = rem & 31;
        int n = nt * 8 + (lane >> 2);
        int k0 = ks * 16 + (lane & 3) * 2;
        float w[4];
        #pragma unroll
        for (int q = 0; q < 4; q++) {
            int k = k0 + (q >> 1) * 8 + (q & 1);
            float v = 0.f;
            if (k < H_) v = Whh[n * H_ + k];
            else if (k < H_ + FE_) v = Wih[(size_t)n * KX_ + k];   // jets cols, ALL gates
            w[q] = v;
        }
        uint2 hiv = make_uint2(pack_h2(w[0], w[1]), pack_h2(w[2], w[3]));
        uint2* bp = (uint2*)g_Bp;
        int p = nt >> 1, half = nt & 1;
        bp[(ks * 768 + p * 32 + lane) * 2 + half] = hiv;
        return;
    }

    __shared__ float4 red[256];       // 4 KB
    __shared__ float hsS[4 * H_];     // 2 KB
    __shared__ float msgS[4 * H_];    // 2 KB
    const int b0 = bid * 4;

    // ---- rowsum for 4 batches ----
    #pragma unroll 1
    for (int bb = 0; bb < 4; bb++) {
        const int k4 = tid & 31, n0 = tid >> 5;
        const float4* p = (const float4*)(h + (size_t)(b0 + bb) * N_ * H_) + k4;
        float4 s = make_float4(0.f, 0.f, 0.f, 0.f);
        #pragma unroll
        for (int j = 0; j < 16; j++) {
            float4 v = p[(size_t)(n0 + 8 * j) * 32];
            s.x += v.x; s.y += v.y; s.z += v.z; s.w += v.w;
        }
        red[tid] = s;
        __syncthreads();
        #pragma unroll
        for (int off = 128; off >= 32; off >>= 1) {
            if (tid < off) {
                float4 a = red[tid], c = red[tid + off];
                a.x += c.x; a.y += c.y; a.z += c.z; a.w += c.w;
                red[tid] = a;
            }
            __syncthreads();
        }
        if (tid < 32) *(float4*)&hsS[bb * H_ + tid * 4] = red[tid];
        __syncthreads();
    }

    // ---- message: thread k for 2 batches (half = tid>>7) ----
    {
        const int k = tid & 127;
        const int bh = (tid >> 7) * 2;
        const float4* wr = (const float4*)(Wm + (size_t)k * H_);
        float a0 = 0.f, a1 = 0.f;
        #pragma unroll 8
        for (int j = 0; j < H_ / 4; j++) {
            float4 w = wr[j];
            const float* m0 = hsS + bh * H_ + 4 * j;
            const float* m1 = hsS + (bh + 1) * H_ + 4 * j;
            a0 += m0[0] * w.x + m0[1] * w.y + m0[2] * w.z + m0[3] * w.w;
            a1 += m1[0] * w.x + m1[1] * w.y + m1[2] * w.z + m1[3] * w.w;
        }
        float bb = (float)N_ * bm[k];
        msgS[bh * H_ + k]       = tanhf(a0 + bb);
        msgS[(bh + 1) * H_ + k] = tanhf(a1 + bb);
    }
    __syncthreads();

    // ---- bias GEMM: g across threads, 4 batches per thread ----
    for (int g = tid; g < G3_; g += 256) {
        const float4* wr = (const float4*)(Wih + (size_t)g * KX_);
        float acc[4] = {0.f, 0.f, 0.f, 0.f};
        #pragma unroll 8
        for (int j = 0; j < H_ / 4; j++) {
            float4 w = wr[j];
            #pragma unroll
            for (int b = 0; b < 4; b++) {
                const float* m = msgS + b * H_ + 4 * j;
                acc[b] += m[0] * w.x + m[1] * w.y + m[2] * w.z + m[3] * w.w;
            }
        }
        float base = bih[g] + ((g < 2 * H_) ? bhh[g] : 0.f);
        #pragma unroll
        for (int b = 0; b < 4; b++)
            g_bias[(size_t)(b0 + b) * G3_ + g] = acc[b] + base;
    }
}

// ---------------- smem layout for k_main (bytes) ----------------
#define OFF_AH   0            //  9728  A_hi [32][152] fp16, 304B row stride
#define OFF_BIAS 9728         //  1536
#define OFF_BHHN 11264        //   512
#define SMEM_SZ  11776

// ---------------- main: 256 threads, 32 rows x 384 cols per CTA, 2 CTAs/SM (PDL) ----------------
__global__ void __launch_bounds__(256, 2) k_main(
    const float* __restrict__ h, const float* __restrict__ jets,
    const float* __restrict__ bhh, float* __restrict__ out)
{
    extern __shared__ char smem[];
    const int tid  = threadIdx.x;
    const int wn   = tid >> 5;          // 8 N-positions: 16 cols per gate each
    const int lane = tid & 31;
    const int cta  = blockIdx.x;        // 32 rows each, 4 CTAs per batch
    const int batch = cta >> 2;
    const float* hTile = h + (size_t)cta * 32 * 128;

    // ======== upstream-independent prologue (overlaps k_pre via PDL) ========
    // ---- convert h -> A_hi only (epilogue re-reads exact h from gmem/L1) ----
    {
        const float4* hp = (const float4*)hTile;
        #pragma unroll
        for (int i = tid; i < 512; i += 256) {
            int row = i >> 4, q = i & 15;            // 8 cols per step
            float4 v0 = hp[(row << 5) + q * 2];
            float4 v1 = hp[(row << 5) + q * 2 + 1];
            uint4 hi4 = make_uint4(pack_h2(v0.x, v0.y), pack_h2(v0.z, v0.w),
                                   pack_h2(v1.x, v1.y), pack_h2(v1.z, v1.w));
            *(uint4*)(smem + OFF_AH + row * 304 + q * 16) = hi4;
        }
    }
    // ---- jets cols (A K 128..143) + zero pad to 152 ----
    if (tid < 32) {
        int row = tid;
        const float4* jp = (const float4*)(jets + (size_t)(cta * 32 + row) * FE_);
        float4 j0 = jp[0], j1 = jp[1];
        uint4 jh = make_uint4(pack_h2(j0.x, j0.y), pack_h2(j0.z, j0.w),
                              pack_h2(j1.x, j1.y), pack_h2(j1.z, j1.w));
        uint4 zz = make_uint4(0, 0, 0, 0);
        *(uint4*)(smem + OFF_AH + row * 304 + 256) = jh;
        *(uint4*)(smem + OFF_AH + row * 304 + 272) = zz;
        *(uint4*)(smem + OFF_AH + row * 304 + 288) = zz;
    }
    // ---- bhh_n (pure input, safe pre-wait) ----
    if (tid < 128)
        ((float*)(smem + OFF_BHHN))[tid] = bhh[2 * H_ + tid];

    // ======== wait for k_pre grid ========
    griddep_wait();

    for (int g = tid; g < G3_; g += 256)
        ((float*)(smem + OFF_BIAS))[g] = g_bias[(size_t)batch * G3_ + g];
    __syncthreads();   // the ONLY barrier

    // acc[gate][mt][j][frag] + accJ (jets . W_ihn, NOT scaled by r)
    float acc[3][2][2][4];
    float accJ[2][2][4];
    #pragma unroll
    for (int g = 0; g < 3; g++)
        #pragma unroll
        for (int m = 0; m < 2; m++)
            #pragma unroll
            for (int j = 0; j < 2; j++) {
                acc[g][m][j][0] = 0.f; acc[g][m][j][1] = 0.f;
                acc[g][m][j][2] = 0.f; acc[g][m][j][3] = 0.f;
            }
    #pragma unroll
    for (int m = 0; m < 2; m++)
        #pragma unroll
        for (int j = 0; j < 2; j++) {
            accJ[m][j][0] = 0.f; accJ[m][j][1] = 0.f;
            accJ[m][j][2] = 0.f; accJ[m][j][3] = 0.f;
        }

    const uint32_t sbA = smem_u32(smem) + OFF_AH
                       + (uint32_t)(lane & 15) * 304 + ((lane & 16) ? 16 : 0);
    const uint4* bBase = g_Bp + wn * 32 + lane;

    #pragma unroll
    for (int ks = 0; ks < KSTEPS; ks++) {
        // A_hi fragments via ldmatrix (2 m-tiles)
        uint32_t ah[2][4];
        ldm_x4(ah[0], sbA + ks * 32);
        ldm_x4(ah[1], sbA + 16 * 304 + ks * 32);
        // B_hi fragments direct from global (L1-resident across CTAs)
        const uint4* bp = bBase + ks * 768;
        #pragma unroll
        for (int g = 0; g < 3; g++) {
            uint4 bh = bp[g * 256];
            float (*dst)[2][4] = (ks == KSTEPS - 1 && g == 2) ? accJ : acc[g];
            #pragma unroll
            for (int mt = 0; mt < 2; mt++) {
                MMA16816(dst[mt][0], ah[mt][0], ah[mt][1], ah[mt][2], ah[mt][3], bh.x, bh.y);
                MMA16816(dst[mt][1], ah[mt][0], ah[mt][1], ah[mt][2], ah[mt][3], bh.z, bh.w);
            }
        }
    }

    // ---- GRU epilogue (warp-local, MUFU tanh; exact h re-read from gmem/L1) ----
    {
        const float* biasS = (const float*)(smem + OFF_BIAS);
        const float* bhhnS = (const float*)(smem + OFF_BHHN);
        const size_t mBase = (size_t)cta * 32;
        #pragma unroll
        for (int mt = 0; mt < 2; mt++) {
            #pragma unroll
            for (int half = 0; half < 2; half++) {
                const int row = mt * 16 + (lane >> 2) + half * 8;
                #pragma unroll
                for (int j = 0; j < 2; j++) {
                    const int c = wn * 16 + j * 8 + (lane & 3) * 2;
                    float2 hv2 = *(const float2*)(hTile + row * 128 + c);
                    float o[2];
                    #pragma unroll
                    for (int e = 0; e < 2; e++) {
                        const int g = c + e;
                        const int fr = half * 2 + e;
                        float aR = acc[0][mt][j][fr];
                        float aZ = acc[1][mt][j][fr];
                        float aN = acc[2][mt][j][fr];
                        float aJ = accJ[mt][j][fr];
                        float r = 0.5f * tanh_ap(0.5f * (aR + biasS[g])) + 0.5f;
                        float z = 0.5f * tanh_ap(0.5f * (aZ + biasS[128 + g])) + 0.5f;
                        float n = tanh_ap(aJ + biasS[256 + g] + r * (aN + bhhnS[g]));
                        float hv = e ? hv2.y : hv2.x;
                        o[e] = (1.f - z) * n + z * hv;
                    }
                    *(float2*)(out + (mBase + row) * 128 + c) = make_float2(o[0], o[1]);
                }
            }
        }
    }
}

extern "C" void kernel_launch(void* const* d_in, const int* in_sizes, int n_in,
                              void* d_out, int out_size) {
    const float* h    = (const float*)d_in[0];
    const float* jets = (const float*)d_in[1];
    // d_in[2] = mask (unused)
    const float* Wm   = (const float*)d_in[3];
    const float* bm   = (const float*)d_in[4];
    const float* Wih  = (const float*)d_in[5];
    const float* Whh  = (const float*)d_in[6];
    const float* bih  = (const float*)d_in[7];
    const float* bhh  = (const float*)d_in[8];
    float* out = (float*)d_out;

    cudaFuncSetAttribute(k_main, cudaFuncAttributeMaxDynamicSharedMemorySize, SMEM_SZ);

    // fused pre-kernel: normal launch
    k_pre<<<310, 256>>>(h, Whh, Wih, Wm, bm, bih, bhh);

    // k_main: programmatic dependent launch (prologue overlaps k_pre drain)
    cudaLaunchAttribute attr[1];
    attr[0].id = cudaLaunchAttributeProgrammaticStreamSerialization;
    attr[0].val.programmaticStreamSerializationAllowed = 1;

    cudaLaunchConfig_t cfg = {};
    cfg.gridDim = dim3(4 * B_);
    cfg.blockDim = dim3(256);
    cfg.dynamicSmemBytes = SMEM_SZ;
    cfg.stream = 0;
    cfg.attrs = attr;
    cfg.numAttrs = 1;
    cudaLaunchKernelEx(&cfg, k_main, h, jets, bhh, out);
}